// round 6
// baseline (speedup 1.0000x reference)
#include <cuda_runtime.h>

// AlarmworkRNN collapsed to a vector RNN (only sequence row 2047 matters).
// Round 6: decomposed (U pre-GEMM / recurrence / out post-GEMM), recurrence
// loop minimized: 64 CTAs, 1 output-pair per warp, interleaved {z12,z2}
// state (one load stream feeds both dots), all-lane redundant tanh,
// 2 syncthreads + 1 counter barrier per step.

#define GRID  64
#define BLOCK 512
#define NSTEP 256

__device__ unsigned g_arrive;
__device__ float2 g_zz[2][1024];          // parity-buffered {z12, z2}
__device__ float g_U[2][NSTEP][1024];     // u1/u2 per step (bias folded)
__device__ float g_hist[NSTEP][1024];     // z1(i+1) published at slot i

__global__ void rnn_init_kernel() {
    int tid = threadIdx.x;
    if (tid == 0) g_arrive = 0u;
    g_zz[0][tid] = make_float2(0.0f, 0.0f);   // blockDim = 1024
}

__device__ __forceinline__ void arrive_release(unsigned* p) {
    asm volatile("red.release.gpu.global.add.u32 [%0], %1;"
                 :: "l"(p), "r"(1u) : "memory");
}
__device__ __forceinline__ unsigned ld_acquire_gpu(unsigned* p) {
    unsigned v;
    asm volatile("ld.acquire.gpu.global.u32 %0, [%1];"
                 : "=r"(v) : "l"(p) : "memory");
    return v;
}
__device__ __forceinline__ float4 ldcg4(const float4* p) {
    float4 u;
    asm volatile("ld.global.cg.v4.f32 {%0,%1,%2,%3}, [%4];"
                 : "=f"(u.x), "=f"(u.y), "=f"(u.z), "=f"(u.w)
                 : "l"(p) : "memory");
    return u;
}
__device__ __forceinline__ float ldcg1(const float* p) {
    float u;
    asm volatile("ld.global.cg.f32 %0, [%1];" : "=f"(u) : "l"(p) : "memory");
    return u;
}

// ---- k1: U[m][t][j] = x[t,2047,:] @ W_in_m[:,j] + b_m[j] ----
// grid 256: m = b>>7, jt = (b>>5)&3 (256 j), tt = b&31 (8 steps)
__global__ __launch_bounds__(256)
void u_kernel(const float* __restrict__ x,
              const float* __restrict__ W_in1, const float* __restrict__ b_in1,
              const float* __restrict__ W_in2, const float* __restrict__ b_in2)
{
    __shared__ float xs[8][256];
    const int b   = blockIdx.x;
    const int m   = b >> 7;
    const int jt  = (b >> 5) & 3;
    const int tt  = b & 31;
    const int t0  = tt * 8;
    const int tid = threadIdx.x;
    const float* W  = m ? W_in2 : W_in1;
    const float* bi = m ? b_in2 : b_in1;

    for (int i = tid; i < 8 * 256; i += 256) {
        int tr = i >> 8, k = i & 255;
        xs[tr][k] = x[((size_t)(t0 + tr) * 2048 + 2047) * 256 + k];
    }
    __syncthreads();

    const int j = jt * 256 + tid;
    float acc[8];
    const float bj = bi[j];
    #pragma unroll
    for (int r = 0; r < 8; r++) acc[r] = bj;
    #pragma unroll 8
    for (int k = 0; k < 256; k++) {
        float w = W[k * 1024 + j];
        #pragma unroll
        for (int r = 0; r < 8; r++) acc[r] += xs[r][k] * w;
    }
    #pragma unroll
    for (int r = 0; r < 8; r++) g_U[m][t0 + r][j] = acc[r];
}

// ---- k3: out[t][o] = tanh(hist[t] @ W_out[:,o] + b_out[o]) ----
// grid 128: 2 steps per block
__global__ __launch_bounds__(256)
void out_kernel(const float* __restrict__ W_out,
                const float* __restrict__ b_out,
                float* __restrict__ out)
{
    __shared__ float zs[2][1024];
    const int t0  = blockIdx.x * 2;
    const int tid = threadIdx.x;
    for (int i = tid; i < 2 * 1024; i += 256)
        zs[i >> 10][i & 1023] = g_hist[t0 + (i >> 10)][i & 1023];
    __syncthreads();

    float a0 = b_out[tid], a1 = a0;
    #pragma unroll 16
    for (int jj = 0; jj < 1024; jj++) {
        float w = W_out[jj * 256 + tid];
        a0 += zs[0][jj] * w;
        a1 += zs[1][jj] * w;
    }
    out[(size_t)t0 * 256 + tid]       = tanhf(a0);
    out[(size_t)(t0 + 1) * 256 + tid] = tanhf(a1);
}

// ---- k2: persistent recurrence ----
__global__ __launch_bounds__(BLOCK, 1)
void rnn_main_kernel(const float* __restrict__ W_rec1,
                     const float* __restrict__ W_rec2)
{
    extern __shared__ float stage[];    // [1024][17] padded (preload only)

    const int tid  = threadIdx.x;
    const int warp = tid >> 5;
    const int lane = tid & 31;
    const int j0   = blockIdx.x * 16;
    const int j    = j0 + warp;          // this warp's output pair

    // ---- weight preload into registers ----
    // wA[2c]/wA[2c+1] multiply z12[k0], z12[k0+1]; k0 = 2*(c*32+lane)
    float wA[32], wB[32];
    for (int idx = tid; idx < 1024 * 16; idx += BLOCK) {
        int k = idx >> 4, jj = idx & 15;
        stage[k * 17 + jj] = W_rec1[k * 1024 + j0 + jj];
    }
    __syncthreads();
    #pragma unroll
    for (int c = 0; c < 16; c++) {
        int k0 = 2 * (c * 32 + lane);
        wA[2*c]   = stage[k0 * 17 + warp];
        wA[2*c+1] = stage[(k0 + 1) * 17 + warp];
    }
    __syncthreads();
    for (int idx = tid; idx < 1024 * 16; idx += BLOCK) {
        int k = idx >> 4, jj = idx & 15;
        stage[k * 17 + jj] = W_rec2[k * 1024 + j0 + jj];
    }
    __syncthreads();
    #pragma unroll
    for (int c = 0; c < 16; c++) {
        int k0 = 2 * (c * 32 + lane);
        wB[2*c]   = stage[k0 * 17 + warp];
        wB[2*c+1] = stage[(k0 + 1) * 17 + warp];
    }
    __syncthreads();

    float z2reg = 0.0f;

    for (int i = 0; i < NSTEP; i++) {
        const int par = i & 1;

        // warp-uniform u loads (broadcast), overlap with state loads below
        float u1 = ldcg1(&g_U[0][i][j]);
        float u2 = ((i & 1) == 0) ? ldcg1(&g_U[1][i][j]) : 0.0f;

        // both dots from one interleaved load stream
        const float4* src = (const float4*)g_zz[par];
        float a = 0.0f, b = 0.0f;
        #pragma unroll
        for (int c = 0; c < 16; c++) {
            float4 q = ldcg4(src + c * 32 + lane);
            a += wA[2*c] * q.x + wA[2*c+1] * q.z;    // z12 terms
            b += wB[2*c] * q.y + wB[2*c+1] * q.w;    // z2  terms
        }
        #pragma unroll
        for (int off = 16; off; off >>= 1) {
            a += __shfl_xor_sync(0xffffffffu, a, off);
            b += __shfl_xor_sync(0xffffffffu, b, off);
        }

        float z1n = tanhf(a + u1);                    // all lanes (redundant)
        if ((i & 1) == 0) z2reg = tanhf(b + u2);      // even: update, odd: hold

        if (lane == 0) {
            g_zz[par ^ 1][j] = make_float2(z1n + z2reg, z2reg);
            g_hist[i][j] = z1n;
        }
        __syncthreads();

        if (i + 1 < NSTEP) {
            if (tid == 0) {
                arrive_release(&g_arrive);
                const unsigned target = (unsigned)(i + 1) * GRID;
                while (ld_acquire_gpu(&g_arrive) < target) { }
            }
            __syncthreads();
        }
    }
}

extern "C" void kernel_launch(void* const* d_in, const int* in_sizes, int n_in,
                              void* d_out, int out_size) {
    (void)in_sizes; (void)n_in; (void)out_size;
    const float* x      = (const float*)d_in[0];
    const float* W_in1  = (const float*)d_in[1];
    const float* b_in1  = (const float*)d_in[2];
    const float* W_rec1 = (const float*)d_in[3];
    const float* W_in2  = (const float*)d_in[4];
    const float* b_in2  = (const float*)d_in[5];
    const float* W_rec2 = (const float*)d_in[6];
    const float* W_out  = (const float*)d_in[7];
    const float* b_out  = (const float*)d_in[8];
    float* out = (float*)d_out;

    const size_t smem_bytes = (size_t)1024 * 17 * sizeof(float);  // 69632
    cudaFuncSetAttribute(rnn_main_kernel,
                         cudaFuncAttributeMaxDynamicSharedMemorySize,
                         (int)smem_bytes);

    rnn_init_kernel<<<1, 1024>>>();
    u_kernel<<<256, 256>>>(x, W_in1, b_in1, W_in2, b_in2);
    rnn_main_kernel<<<GRID, BLOCK, smem_bytes>>>(W_rec1, W_rec2);
    out_kernel<<<128, 256>>>(W_out, b_out, out);
}

// round 7
// speedup vs baseline: 1.6030x; 1.6030x over previous
#include <cuda_runtime.h>

// AlarmworkRNN collapsed to a vector RNN (only sequence row 2047 matters).
// Round 7: U pre-GEMM + out post-GEMM (kept from R5/R6) with the recurrence
// rebuilt on R3's SMEM-staged state (the only structure that benched well):
//   - state {z1,z2} reloaded once per CTA into SMEM (1 LDG.128/thread)
//   - one warp per output, full K=1024: no partials, no publisher warp
//   - 3 syncthreads + 1 counter barrier per step

#define GRID  128
#define BLOCK 512
#define NSTEP 256

__device__ unsigned g_arrive;
__device__ float2 g_z[2][1024];           // parity-buffered {z1, z2}
__device__ float g_U[2][NSTEP][1024];     // u1/u2 per step (bias folded)
__device__ float g_hist[NSTEP][1024];     // z1 history for out_kernel

__global__ void rnn_init_kernel() {
    int tid = threadIdx.x;
    if (tid == 0) g_arrive = 0u;
    g_z[0][tid] = make_float2(0.0f, 0.0f);    // blockDim = 1024
}

__device__ __forceinline__ void arrive_release(unsigned* p) {
    asm volatile("red.release.gpu.global.add.u32 [%0], %1;"
                 :: "l"(p), "r"(1u) : "memory");
}
__device__ __forceinline__ unsigned ld_acquire_gpu(unsigned* p) {
    unsigned v;
    asm volatile("ld.acquire.gpu.global.u32 %0, [%1];"
                 : "=r"(v) : "l"(p) : "memory");
    return v;
}
__device__ __forceinline__ float4 ldcg4(const float4* p) {
    float4 u;
    asm volatile("ld.global.cg.v4.f32 {%0,%1,%2,%3}, [%4];"
                 : "=f"(u.x), "=f"(u.y), "=f"(u.z), "=f"(u.w)
                 : "l"(p) : "memory");
    return u;
}

// ---- k1: U[m][t][j] = x[t,2047,:] @ W_in_m[:,j] + b_m[j] ----
__global__ __launch_bounds__(256)
void u_kernel(const float* __restrict__ x,
              const float* __restrict__ W_in1, const float* __restrict__ b_in1,
              const float* __restrict__ W_in2, const float* __restrict__ b_in2)
{
    __shared__ float xs[8][256];
    const int b   = blockIdx.x;
    const int m   = b >> 7;
    const int jt  = (b >> 5) & 3;
    const int tt  = b & 31;
    const int t0  = tt * 8;
    const int tid = threadIdx.x;
    const float* W  = m ? W_in2 : W_in1;
    const float* bi = m ? b_in2 : b_in1;

    for (int i = tid; i < 8 * 256; i += 256) {
        int tr = i >> 8, k = i & 255;
        xs[tr][k] = x[((size_t)(t0 + tr) * 2048 + 2047) * 256 + k];
    }
    __syncthreads();

    const int j = jt * 256 + tid;
    float acc[8];
    const float bj = bi[j];
    #pragma unroll
    for (int r = 0; r < 8; r++) acc[r] = bj;
    #pragma unroll 8
    for (int k = 0; k < 256; k++) {
        float w = W[k * 1024 + j];
        #pragma unroll
        for (int r = 0; r < 8; r++) acc[r] += xs[r][k] * w;
    }
    #pragma unroll
    for (int r = 0; r < 8; r++) g_U[m][t0 + r][j] = acc[r];
}

// ---- k3: out[t][o] = tanh(hist[t] @ W_out[:,o] + b_out[o]) ----
__global__ __launch_bounds__(256)
void out_kernel(const float* __restrict__ W_out,
                const float* __restrict__ b_out,
                float* __restrict__ out)
{
    __shared__ float zs[2][1024];
    const int t0  = blockIdx.x * 2;
    const int tid = threadIdx.x;
    for (int i = tid; i < 2 * 1024; i += 256)
        zs[i >> 10][i & 1023] = g_hist[t0 + (i >> 10)][i & 1023];
    __syncthreads();

    float a0 = b_out[tid], a1 = a0;
    #pragma unroll 16
    for (int jj = 0; jj < 1024; jj++) {
        float w = W_out[jj * 256 + tid];
        a0 += zs[0][jj] * w;
        a1 += zs[1][jj] * w;
    }
    out[(size_t)t0 * 256 + tid]       = tanhf(a0);
    out[(size_t)(t0 + 1) * 256 + tid] = tanhf(a1);
}

// ---- k2: persistent recurrence ----
__global__ __launch_bounds__(BLOCK, 1)
void rnn_main_kernel(const float* __restrict__ W_rec1,
                     const float* __restrict__ W_rec2)
{
    __shared__ float e1[1024];          // z1 + z2
    __shared__ float e2[1024];          // z2
    __shared__ float stage[1024 * 9];   // weight staging (preload only), pad 9

    const int tid  = threadIdx.x;
    const int warp = tid >> 5;
    const int lane = tid & 31;
    const int j0   = blockIdx.x * 8;
    const int role = warp >> 3;         // 0: z1 warps 0-7, 1: z2 warps 8-15
    const int jl   = warp & 7;
    const int j    = j0 + jl;           // this warp's output index

    // ---- weight preload: wreg[4c+s] = W[(c*128 + lane*4 + s)][j] ----
    float wreg[32];
    for (int round = 0; round < 2; round++) {
        const float* W = round ? W_rec2 : W_rec1;
        for (int idx = tid; idx < 1024 * 8; idx += BLOCK) {
            int k = idx >> 3, c = idx & 7;
            stage[k * 9 + c] = W[k * 1024 + j0 + c];
        }
        __syncthreads();
        if (role == round) {
            #pragma unroll
            for (int c = 0; c < 8; c++) {
                int k0 = c * 128 + lane * 4;
                wreg[4*c+0] = stage[(k0 + 0) * 9 + jl];
                wreg[4*c+1] = stage[(k0 + 1) * 9 + jl];
                wreg[4*c+2] = stage[(k0 + 2) * 9 + jl];
                wreg[4*c+3] = stage[(k0 + 3) * 9 + jl];
            }
        }
        __syncthreads();
    }

    float z2reg = 0.0f;                 // z2 warps, lane-replicated hold value

    for (int i = 0; i < NSTEP; i++) {
        const int par = i & 1;
        const int pw  = par ^ 1;

        // warp-uniform u load (broadcast LDG) — consumed late, mostly hidden
        const float u = g_U[role][i][j];

        // Phase A: reload state once per CTA into SMEM
        {
            float4 q = ldcg4(((const float4*)g_z[par]) + tid);  // {z1a,z2a,z1b,z2b}
            ((float2*)e1)[tid] = make_float2(q.x + q.y, q.z + q.w);
            ((float2*)e2)[tid] = make_float2(q.y, q.w);
        }
        __syncthreads();

        // Phase B: one warp = one full-K dot
        if (role == 0 || (i & 1) == 0) {
            const float4* ev = (const float4*)(role ? e2 : e1);
            float a0 = 0.0f, a1 = 0.0f;
            #pragma unroll
            for (int c = 0; c < 8; c++) {
                float4 q = ev[c * 32 + lane];
                a0 += wreg[4*c+0] * q.x + wreg[4*c+1] * q.y;
                a1 += wreg[4*c+2] * q.z + wreg[4*c+3] * q.w;
            }
            float acc = a0 + a1;
            #pragma unroll
            for (int off = 16; off; off >>= 1)
                acc += __shfl_xor_sync(0xffffffffu, acc, off);
            if (role == 0) {
                if (lane == 0) {
                    float v = tanhf(acc + u);
                    ((float*)&g_z[pw][j])[0] = v;     // z1
                    g_hist[i][j] = v;
                }
            } else {
                z2reg = tanhf(acc + u);               // all lanes (redundant)
                if (lane == 0) ((float*)&g_z[pw][j])[1] = z2reg;
            }
        } else if (lane == 0) {
            ((float*)&g_z[pw][j])[1] = z2reg;         // odd step: z2 holds
        }
        __syncthreads();    // all publishes issued (ordering for tid0's release)

        if (i + 1 < NSTEP) {
            if (tid == 0) {
                arrive_release(&g_arrive);
                const unsigned target = (unsigned)(i + 1) * GRID;
                while (ld_acquire_gpu(&g_arrive) < target) { }
            }
            __syncthreads();
        }
    }
}

extern "C" void kernel_launch(void* const* d_in, const int* in_sizes, int n_in,
                              void* d_out, int out_size) {
    (void)in_sizes; (void)n_in; (void)out_size;
    const float* x      = (const float*)d_in[0];
    const float* W_in1  = (const float*)d_in[1];
    const float* b_in1  = (const float*)d_in[2];
    const float* W_rec1 = (const float*)d_in[3];
    const float* W_in2  = (const float*)d_in[4];
    const float* b_in2  = (const float*)d_in[5];
    const float* W_rec2 = (const float*)d_in[6];
    const float* W_out  = (const float*)d_in[7];
    const float* b_out  = (const float*)d_in[8];
    float* out = (float*)d_out;

    rnn_init_kernel<<<1, 1024>>>();
    u_kernel<<<256, 256>>>(x, W_in1, b_in1, W_in2, b_in2);
    rnn_main_kernel<<<GRID, BLOCK>>>(W_rec1, W_rec2);
    out_kernel<<<128, 256>>>(W_out, b_out, out);
}

// round 9
// speedup vs baseline: 1.6276x; 1.0154x over previous
#include <cuda_runtime.h>

// AlarmworkRNN collapsed to a vector RNN (only sequence row 2047 matters).
// Round 9: R8's out-fold (out-GEMV in odd steps' idle z2-warps, no out_kernel)
// with the R7 counter barrier restored verbatim (R8's flag barrier hung).

#define GRID  128
#define BLOCK 512
#define NSTEP 256

__device__ unsigned g_arrive;
__device__ float2 g_z[2][1024];           // parity-buffered {z1, z2}
__device__ float g_U[2][NSTEP][1024];     // u1/u2 per step (bias folded)

__global__ void rnn_init_kernel() {
    int tid = threadIdx.x;
    if (tid == 0) g_arrive = 0u;
    g_z[0][tid] = make_float2(0.0f, 0.0f);    // blockDim = 1024
}

__device__ __forceinline__ void arrive_release(unsigned* p) {
    asm volatile("red.release.gpu.global.add.u32 [%0], %1;"
                 :: "l"(p), "r"(1u) : "memory");
}
__device__ __forceinline__ unsigned ld_acquire_gpu(unsigned* p) {
    unsigned v;
    asm volatile("ld.acquire.gpu.global.u32 %0, [%1];"
                 : "=r"(v) : "l"(p) : "memory");
    return v;
}
__device__ __forceinline__ float4 ldcg4(const float4* p) {
    float4 u;
    asm volatile("ld.global.cg.v4.f32 {%0,%1,%2,%3}, [%4];"
                 : "=f"(u.x), "=f"(u.y), "=f"(u.z), "=f"(u.w)
                 : "l"(p) : "memory");
    return u;
}

// ---- k1: U[m][t][j] = x[t,2047,:] @ W_in_m[:,j] + b_m[j] ----
__global__ __launch_bounds__(256)
void u_kernel(const float* __restrict__ x,
              const float* __restrict__ W_in1, const float* __restrict__ b_in1,
              const float* __restrict__ W_in2, const float* __restrict__ b_in2)
{
    __shared__ float xs[8][256];
    const int b   = blockIdx.x;
    const int m   = b >> 7;
    const int jt  = (b >> 5) & 3;
    const int t0  = (b & 31) * 8;
    const int tid = threadIdx.x;
    const float* W  = m ? W_in2 : W_in1;
    const float* bi = m ? b_in2 : b_in1;

    for (int i = tid; i < 8 * 256; i += 256) {
        int tr = i >> 8, k = i & 255;
        xs[tr][k] = x[((size_t)(t0 + tr) * 2048 + 2047) * 256 + k];
    }
    __syncthreads();

    const int j = jt * 256 + tid;
    float acc[8];
    const float bj = bi[j];
    #pragma unroll
    for (int r = 0; r < 8; r++) acc[r] = bj;
    #pragma unroll 8
    for (int k = 0; k < 256; k++) {
        float w = W[k * 1024 + j];
        #pragma unroll
        for (int r = 0; r < 8; r++) acc[r] += xs[r][k] * w;
    }
    #pragma unroll
    for (int r = 0; r < 8; r++) g_U[m][t0 + r][j] = acc[r];
}

// ---- k2: persistent recurrence + in-loop out ----
__global__ __launch_bounds__(BLOCK, 1)
void rnn_main_kernel(const float* __restrict__ W_rec1,
                     const float* __restrict__ W_rec2,
                     const float* __restrict__ W_out,
                     const float* __restrict__ b_out,
                     float* __restrict__ out)
{
    extern __shared__ float sm[];
    float* e1     = sm;                 // [1024]  z1 + z2
    float* e2     = e1 + 1024;          // [1024]  z2
    float* z1s    = e2 + 1024;          // [2][1024] z1 snapshots by parity
    float* wout_s = z1s + 2048;         // [2][1024] this CTA's W_out columns
    float* stage  = wout_s + 2048;      // [1024*9] weight staging (preload only)

    const int tid  = threadIdx.x;
    const int warp = tid >> 5;
    const int lane = tid & 31;
    const int j0   = blockIdx.x * 8;
    const int o0   = blockIdx.x * 2;
    const int role = warp >> 3;         // 0: z1 warps 0-7, 1: z2 warps 8-15
    const int jl   = warp & 7;
    const int j    = j0 + jl;

    // ---- preload recurrent weights into registers ----
    float wreg[32];
    for (int round = 0; round < 2; round++) {
        const float* W = round ? W_rec2 : W_rec1;
        for (int idx = tid; idx < 1024 * 8; idx += BLOCK) {
            int k = idx >> 3, c = idx & 7;
            stage[k * 9 + c] = W[k * 1024 + j0 + c];
        }
        __syncthreads();
        if (role == round) {
            #pragma unroll
            for (int c = 0; c < 8; c++) {
                int k0 = c * 128 + lane * 4;
                wreg[4*c+0] = stage[(k0 + 0) * 9 + jl];
                wreg[4*c+1] = stage[(k0 + 1) * 9 + jl];
                wreg[4*c+2] = stage[(k0 + 2) * 9 + jl];
                wreg[4*c+3] = stage[(k0 + 3) * 9 + jl];
            }
        }
        __syncthreads();
    }

    // preload this CTA's two W_out columns + biases into SMEM
    for (int idx = tid; idx < 2048; idx += BLOCK) {
        int jj = idx >> 1, c = idx & 1;
        wout_s[c * 1024 + jj] = W_out[jj * 256 + o0 + c];
    }
    const int   ow   = warp - 8;                 // out-warp id 0..3 (warps 8-11)
    const float obia = (ow >= 0 && ow < 4) ? b_out[o0 + (ow & 1)] : 0.0f;
    __syncthreads();

    float z2reg = 0.0f;

    for (int i = 0; i < NSTEP; i++) {
        const int par = i & 1;
        const int pw  = par ^ 1;

        const float u = g_U[role][i][j];   // warp-uniform broadcast

        // Phase A: stage state into SMEM (+ z1 snapshot for out-GEMV)
        {
            float4 q = ldcg4(((const float4*)g_z[par]) + tid); // {z1a,z2a,z1b,z2b}
            ((float2*)e1)[tid]  = make_float2(q.x + q.y, q.z + q.w);
            ((float2*)e2)[tid]  = make_float2(q.y, q.w);
            ((float2*)(z1s + par * 1024))[tid] = make_float2(q.x, q.z);
        }
        __syncthreads();

        // Phase B: recurrent dots (and, on odd steps, out-GEMV in warps 8-11)
        if (role == 0 || (i & 1) == 0) {
            const float4* ev = (const float4*)(role ? e2 : e1);
            float a0 = 0.0f, a1 = 0.0f;
            #pragma unroll
            for (int c = 0; c < 8; c++) {
                float4 q = ev[c * 32 + lane];
                a0 += wreg[4*c+0] * q.x + wreg[4*c+1] * q.y;
                a1 += wreg[4*c+2] * q.z + wreg[4*c+3] * q.w;
            }
            float acc = a0 + a1;
            #pragma unroll
            for (int off = 16; off; off >>= 1)
                acc += __shfl_xor_sync(0xffffffffu, acc, off);
            if (role == 0) {
                if (lane == 0) ((float*)&g_z[pw][j])[0] = tanhf(acc + u);
            } else {
                z2reg = tanhf(acc + u);
                if (lane == 0) ((float*)&g_z[pw][j])[1] = z2reg;
            }
        } else {
            // odd step: idle z2-warps 8-11 compute out[i-2], out[i-1]
            if (ow >= 0 && ow < 4) {
                const int t_sel = ow >> 1;           // 0: out[i-2], 1: out[i-1]
                const int o_sel = ow & 1;
                if (!(t_sel == 0 && i == 1)) {
                    const float4* wv = (const float4*)(wout_s + o_sel * 1024);
                    const float4* zv = (const float4*)(z1s + t_sel * 1024);
                    float a0 = 0.0f, a1 = 0.0f;
                    #pragma unroll
                    for (int c = 0; c < 8; c++) {
                        float4 wq = wv[c * 32 + lane];
                        float4 zq = zv[c * 32 + lane];
                        a0 += wq.x * zq.x + wq.y * zq.y;
                        a1 += wq.z * zq.z + wq.w * zq.w;
                    }
                    float acc = a0 + a1;
                    #pragma unroll
                    for (int off = 16; off; off >>= 1)
                        acc += __shfl_xor_sync(0xffffffffu, acc, off);
                    if (lane == 0)
                        out[(size_t)(i - 2 + t_sel) * 256 + o0 + o_sel] =
                            tanhf(acc + obia);
                }
            }
        }
        // odd step: publish held z2 (owner z2-warp, lane 0)
        if (role == 1 && (i & 1) == 1 && lane == 0)
            ((float*)&g_z[pw][j])[1] = z2reg;
        __syncthreads();   // all publishes issued before arrive

        // R7 counter barrier (proven)
        if (i + 1 < NSTEP) {
            if (tid == 0) {
                arrive_release(&g_arrive);
                const unsigned target = (unsigned)(i + 1) * GRID;
                while (ld_acquire_gpu(&g_arrive) < target) { }
            }
            __syncthreads();
        }
    }

    // Tail: final barrier round, then out[255] from z1(256)
    if (tid == 0) {
        arrive_release(&g_arrive);
        const unsigned target = (unsigned)NSTEP * GRID;
        while (ld_acquire_gpu(&g_arrive) < target) { }
    }
    __syncthreads();
    {
        float4 q = ldcg4(((const float4*)g_z[0]) + tid);   // z(256) lives in g_z[0]
        ((float2*)z1s)[tid] = make_float2(q.x, q.z);
        __syncthreads();
        if (ow == 0 || ow == 1) {          // warps 8, 9
            const float4* wv = (const float4*)(wout_s + ow * 1024);
            const float4* zv = (const float4*)z1s;
            float a0 = 0.0f, a1 = 0.0f;
            #pragma unroll
            for (int c = 0; c < 8; c++) {
                float4 wq = wv[c * 32 + lane];
                float4 zq = zv[c * 32 + lane];
                a0 += wq.x * zq.x + wq.y * zq.y;
                a1 += wq.z * zq.z + wq.w * zq.w;
            }
            float acc = a0 + a1;
            #pragma unroll
            for (int off = 16; off; off >>= 1)
                acc += __shfl_xor_sync(0xffffffffu, acc, off);
            if (lane == 0)
                out[(size_t)255 * 256 + o0 + ow] = tanhf(acc + b_out[o0 + ow]);
        }
    }
}

extern "C" void kernel_launch(void* const* d_in, const int* in_sizes, int n_in,
                              void* d_out, int out_size) {
    (void)in_sizes; (void)n_in; (void)out_size;
    const float* x      = (const float*)d_in[0];
    const float* W_in1  = (const float*)d_in[1];
    const float* b_in1  = (const float*)d_in[2];
    const float* W_rec1 = (const float*)d_in[3];
    const float* W_in2  = (const float*)d_in[4];
    const float* b_in2  = (const float*)d_in[5];
    const float* W_rec2 = (const float*)d_in[6];
    const float* W_out  = (const float*)d_in[7];
    const float* b_out  = (const float*)d_in[8];
    float* out = (float*)d_out;

    const size_t smem_bytes =
        (size_t)(1024 + 1024 + 2048 + 2048 + 1024 * 9) * sizeof(float); // 61.4 KB
    cudaFuncSetAttribute(rnn_main_kernel,
                         cudaFuncAttributeMaxDynamicSharedMemorySize,
                         (int)smem_bytes);

    rnn_init_kernel<<<1, 1024>>>();
    u_kernel<<<256, 256>>>(x, W_in1, b_in1, W_in2, b_in2);
    rnn_main_kernel<<<GRID, BLOCK, smem_bytes>>>(W_rec1, W_rec2, W_out, b_out, out);
}